// round 3
// baseline (speedup 1.0000x reference)
#include <cuda_runtime.h>
#include <cstdint>

// ---------------------------------------------------------------------------
// Problem constants
// ---------------------------------------------------------------------------
#define B 64
#define N 2048
#define DIM 768
#define POOL 1024
#define LEN 16
#define NOUT 2080                 // 2*LEN + N
#define C4 (DIM / 4)              // 192 float4 per row
#define NCHUNK 16
#define TOKPC (N / NCHUNK)        // 128
#define SCALAR_OFF ((size_t)B * NOUT * DIM)

// ---------------------------------------------------------------------------
// Device scratch (no allocations allowed). NEVER passed from host code —
// host code sees the host shadow symbol, which on GB300 (ATS) is silently
// dereferenceable and points at the WRONG memory. All access is device-side.
// ---------------------------------------------------------------------------
__device__ float4 g_part[B * NCHUNK * C4];   // per-(b,chunk) partial sums, 3 MB
__device__ float  g_xnorm[B * DIM];          // l2-normalized mean embedding
__device__ float  g_resid[B * DIM];          // prompt_key[idx] - x_norm
__device__ float  g_invn_key[POOL];
__device__ float  g_invn_res[POOL];
__device__ float  g_sim[B * POOL];
__device__ float  g_rsim[B * POOL];
__device__ int    g_idx1[B];
__device__ int    g_idx2[B];
__device__ float  g_best1[B];
__device__ float  g_best2[B];

// ---------------------------------------------------------------------------
// 1) Fused: copy x_embed -> out rows [32, 2080)  AND  per-(b,chunk,c) sums.
//    grid = B*16, block = 192 (one float4 column per thread, 128 tokens).
//    Deterministic: partials written once, no atomics.
// ---------------------------------------------------------------------------
__global__ __launch_bounds__(C4) void copy_mean_kernel(
    const float4* __restrict__ x, float4* __restrict__ out4)
{
    int b     = blockIdx.x >> 4;
    int chunk = blockIdx.x & 15;
    int c4    = threadIdx.x;                         // 0..191

    size_t xbase = ((size_t)b * N + (size_t)chunk * TOKPC) * C4 + c4;
    size_t obase = ((size_t)b * NOUT + 2 * LEN + (size_t)chunk * TOKPC) * C4 + c4;

    float ax = 0.f, ay = 0.f, az = 0.f, aw = 0.f;
#pragma unroll 8
    for (int t = 0; t < TOKPC; ++t) {
        float4 v = x[xbase + (size_t)t * C4];
        out4[obase + (size_t)t * C4] = v;
        ax += v.x; ay += v.y; az += v.z; aw += v.w;
    }
    g_part[(b * NCHUNK + chunk) * C4 + c4] = make_float4(ax, ay, az, aw);
}

// ---------------------------------------------------------------------------
// block-wide sum reduce helper (256 threads)
// ---------------------------------------------------------------------------
__device__ __forceinline__ float block_sum_256(float v, float* sh) {
#pragma unroll
    for (int o = 16; o > 0; o >>= 1) v += __shfl_down_sync(0xffffffffu, v, o);
    int warp = threadIdx.x >> 5, lane = threadIdx.x & 31;
    if (lane == 0) sh[warp] = v;
    __syncthreads();
    float t = (threadIdx.x < 8) ? sh[threadIdx.x] : 0.0f;
    if (threadIdx.x < 8) {
#pragma unroll
        for (int o = 4; o > 0; o >>= 1) t += __shfl_down_sync(0xffu, t, o);
        if (threadIdx.x == 0) sh[0] = t;
    }
    __syncthreads();
    return sh[0];
}

// ---------------------------------------------------------------------------
// 2) x_norm = l2norm(mean over tokens)   grid=B, block=192 (one float4 each)
//    Fixed-order sum over the 16 chunk partials -> deterministic.
// ---------------------------------------------------------------------------
__global__ __launch_bounds__(C4) void xnorm_kernel() {
    __shared__ float sh[8];
    int b = blockIdx.x, c4 = threadIdx.x;
    float sx = 0.f, sy = 0.f, sz = 0.f, sw = 0.f;
#pragma unroll
    for (int k = 0; k < NCHUNK; ++k) {
        float4 p = g_part[(b * NCHUNK + k) * C4 + c4];
        sx += p.x; sy += p.y; sz += p.z; sw += p.w;
    }
    const float invN = 1.0f / (float)N;
    sx *= invN; sy *= invN; sz *= invN; sw *= invN;
    float ss = sx * sx + sy * sy + sz * sz + sw * sw;
    // 192-thread block reduce (6 warps)
#pragma unroll
    for (int o = 16; o > 0; o >>= 1) ss += __shfl_down_sync(0xffffffffu, ss, o);
    int warp = threadIdx.x >> 5, lane = threadIdx.x & 31;
    if (lane == 0) sh[warp] = ss;
    __syncthreads();
    if (threadIdx.x == 0) {
        float tot = sh[0] + sh[1] + sh[2] + sh[3] + sh[4] + sh[5];
        sh[0] = rsqrtf(fmaxf(tot, 1e-12f));
    }
    __syncthreads();
    float inv = sh[0];
    float* dst = g_xnorm + b * DIM + c4 * 4;
    dst[0] = sx * inv; dst[1] = sy * inv; dst[2] = sz * inv; dst[3] = sw * inv;
}

// ---------------------------------------------------------------------------
// 3) inverse norms of both key pools   grid=2*POOL, block=256
// ---------------------------------------------------------------------------
__global__ void keynorm_kernel(const float* __restrict__ pk,
                               const float* __restrict__ rpk)
{
    __shared__ float sh[8];
    int p = blockIdx.x;
    const float* src = (p < POOL) ? (pk + (size_t)p * DIM)
                                  : (rpk + (size_t)(p - POOL) * DIM);
    float ss = 0.f;
#pragma unroll
    for (int i = 0; i < 3; ++i) {
        float v = src[threadIdx.x + i * 256];
        ss += v * v;
    }
    float tot = block_sum_256(ss, sh);
    if (threadIdx.x == 0) {
        float inv = rsqrtf(fmaxf(tot, 1e-12f));
        if (p < POOL) g_invn_key[p] = inv;
        else          g_invn_res[p - POOL] = inv;
    }
}

// ---------------------------------------------------------------------------
// 4) sim[b,p] = dot(vec[b], key[p]) * invn[p]
//    STAGE 0: vec=g_xnorm, invn=g_invn_key, out=g_sim
//    STAGE 1: vec=g_resid, invn=g_invn_res, out=g_rsim
//    p-tiled: grid = POOL/16, 16 keys in 48 KB smem, loop over all b.
// ---------------------------------------------------------------------------
template <int STAGE>
__global__ __launch_bounds__(256) void sim_kernel(const float* __restrict__ keys)
{
    const float* vec    = STAGE ? g_resid    : g_xnorm;
    const float* invn   = STAGE ? g_invn_res : g_invn_key;
    float*       simout = STAGE ? g_rsim     : g_sim;

    __shared__ float skey[16 * DIM];   // 48 KB
    int pt = blockIdx.x * 16;
    for (int i = threadIdx.x; i < 16 * DIM; i += 256)
        skey[i] = keys[(size_t)pt * DIM + i];
    __syncthreads();

    int warp = threadIdx.x >> 5, lane = threadIdx.x & 31;
    int p0 = warp * 2, p1 = warp * 2 + 1;
    float i0 = invn[pt + p0], i1 = invn[pt + p1];

    for (int b = 0; b < B; ++b) {
        const float* xb = vec + (size_t)b * DIM;
        float d0 = 0.f, d1 = 0.f;
#pragma unroll
        for (int c = lane; c < DIM; c += 32) {
            float xv = xb[c];
            d0 += xv * skey[p0 * DIM + c];
            d1 += xv * skey[p1 * DIM + c];
        }
#pragma unroll
        for (int o = 16; o > 0; o >>= 1) {
            d0 += __shfl_down_sync(0xffffffffu, d0, o);
            d1 += __shfl_down_sync(0xffffffffu, d1, o);
        }
        if (lane == 0) {
            simout[(size_t)b * POOL + pt + p0] = d0 * i0;
            simout[(size_t)b * POOL + pt + p1] = d1 * i1;
        }
    }
}

// ---------------------------------------------------------------------------
// 5) argmax over p (lowest index wins ties, matching jax top_k).
//    STAGE 0 additionally builds the residual vector. grid=B, block=256
// ---------------------------------------------------------------------------
template <int STAGE>
__global__ void argmax_kernel(const float* __restrict__ pk)
{
    const float* sim = STAGE ? g_rsim : g_sim;
    __shared__ float sv[256];
    __shared__ int   si[256];
    int b = blockIdx.x, tid = threadIdx.x;
    float best = -3.402823466e38f;
    int bi = 0x7fffffff;
    for (int p = tid; p < POOL; p += 256) {
        float v = sim[(size_t)b * POOL + p];
        if (v > best) { best = v; bi = p; }
    }
    sv[tid] = best; si[tid] = bi;
    __syncthreads();
    for (int s = 128; s > 0; s >>= 1) {
        if (tid < s) {
            float v = sv[tid + s]; int i2 = si[tid + s];
            if (v > sv[tid] || (v == sv[tid] && i2 < si[tid])) {
                sv[tid] = v; si[tid] = i2;
            }
        }
        __syncthreads();
    }
    if (tid == 0) {
        if (STAGE) { g_idx2[b] = si[0]; g_best2[b] = sv[0]; }
        else       { g_idx1[b] = si[0]; g_best1[b] = sv[0]; }
    }
    if (!STAGE) {
        __syncthreads();
        int idx = si[0];
#pragma unroll
        for (int i = 0; i < 3; ++i) {
            int c = tid + i * 256;
            g_resid[b * DIM + c] =
                pk[(size_t)idx * DIM + c] - g_xnorm[b * DIM + c];
        }
    }
}

// ---------------------------------------------------------------------------
// 6) gather selected prompts into out rows [0, 32)
//    which=0 -> residual_prompt[g_idx2] @ rows [0,16)
//    which=1 -> prompt[g_idx1]          @ rows [16,32)
// ---------------------------------------------------------------------------
__global__ __launch_bounds__(256) void gather_kernel(
    const float4* __restrict__ prompt4,
    const float4* __restrict__ rprompt4,
    float4* __restrict__ out4)
{
    int b = blockIdx.x >> 1;
    int which = blockIdx.x & 1;
    int idx = which ? g_idx1[b] : g_idx2[b];
    const float4* src = (which ? prompt4 : rprompt4) + (size_t)idx * LEN * C4;
    float4* dst = out4 + ((size_t)b * NOUT + (which ? LEN : 0)) * C4;
    for (int i = threadIdx.x; i < LEN * C4; i += 256)
        dst[i] = src[i];
}

// ---------------------------------------------------------------------------
// 7) scalar: (sum_b best1 + sum_b best2) / B
// ---------------------------------------------------------------------------
__global__ void scalar_kernel(float* __restrict__ out, int write) {
    if (!write) return;
    __shared__ float sh[2];
    float v = (threadIdx.x < B)
                  ? (g_best1[threadIdx.x] + g_best2[threadIdx.x]) : 0.0f;
#pragma unroll
    for (int o = 16; o > 0; o >>= 1) v += __shfl_down_sync(0xffffffffu, v, o);
    if ((threadIdx.x & 31) == 0) sh[threadIdx.x >> 5] = v;
    __syncthreads();
    if (threadIdx.x == 0) out[SCALAR_OFF] = (sh[0] + sh[1]) * (1.0f / (float)B);
}

// ---------------------------------------------------------------------------
// launch
// ---------------------------------------------------------------------------
extern "C" void kernel_launch(void* const* d_in, const int* in_sizes, int n_in,
                              void* d_out, int out_size)
{
    // Map inputs by size (robust to scalar placement): the 100M array is
    // x_embed; 12.58M arrays are prompt then residual_prompt; 786k arrays are
    // prompt_key then residual_prompt_key (relative order preserved by both
    // dict order and alphabetical order).
    const float* x_embed = nullptr;
    const float* prompt = nullptr, * rprompt = nullptr;
    const float* pkey = nullptr, * rpkey = nullptr;
    for (int i = 0; i < n_in; ++i) {
        int sz = in_sizes[i];
        if (sz == B * N * DIM) x_embed = (const float*)d_in[i];
        else if (sz == POOL * LEN * DIM) {
            if (!prompt) prompt = (const float*)d_in[i];
            else if (!rprompt) rprompt = (const float*)d_in[i];
        } else if (sz == POOL * DIM) {
            if (!pkey) pkey = (const float*)d_in[i];
            else if (!rpkey) rpkey = (const float*)d_in[i];
        }
    }
    float* out = (float*)d_out;

    copy_mean_kernel<<<B * NCHUNK, C4>>>((const float4*)x_embed, (float4*)out);
    xnorm_kernel<<<B, C4>>>();
    keynorm_kernel<<<2 * POOL, 256>>>(pkey, rpkey);
    sim_kernel<0><<<POOL / 16, 256>>>(pkey);
    argmax_kernel<0><<<B, 256>>>(pkey);
    sim_kernel<1><<<POOL / 16, 256>>>(rpkey);
    argmax_kernel<1><<<B, 256>>>(rpkey);
    gather_kernel<<<2 * B, 256>>>((const float4*)prompt,
                                  (const float4*)rprompt, (float4*)out);
    int write_scalar = ((size_t)out_size > SCALAR_OFF) ? 1 : 0;
    scalar_kernel<<<1, 64>>>(out, write_scalar);
}

// round 4
// speedup vs baseline: 1.0855x; 1.0855x over previous
#include <cuda_runtime.h>
#include <cstdint>

// ---------------------------------------------------------------------------
// Problem constants
// ---------------------------------------------------------------------------
#define B 64
#define N 2048
#define DIM 768
#define POOL 1024
#define LEN 16
#define NOUT 2080                 // 2*LEN + N
#define C4 (DIM / 4)              // 192 float4 per row
#define NCHUNK 16
#define TOKPC (N / NCHUNK)        // 128
#define SIMP 8                    // p-columns per sim block
#define SCALAR_OFF ((size_t)B * NOUT * DIM)

// ---------------------------------------------------------------------------
// Device scratch (no allocations). Only ever touched from device code —
// host-passing these symbols silently binds the host shadow copy (ATS).
// ---------------------------------------------------------------------------
__device__ __align__(16) float4 g_part[B * NCHUNK * C4];  // per-(b,chunk) sums
__device__ __align__(16) float  g_xnormT[DIM * B];        // x_norm transposed [c][b]
__device__ __align__(16) float  g_residT[DIM * B];        // residual transposed [c][b]
__device__ __align__(16) float  g_simT[POOL * B];         // sim transposed [p][b]
__device__ __align__(16) float  g_rsimT[POOL * B];
__device__ float  g_invn_key[POOL];
__device__ float  g_invn_res[POOL];
__device__ int    g_idx1[B];
__device__ int    g_idx2[B];
__device__ float  g_best1[B];
__device__ float  g_best2[B];

// ---------------------------------------------------------------------------
// 1) Fused: copy x_embed -> out rows [32,2080) AND per-(b,chunk,c) sums.
//    grid = B*16, block = 192. Deterministic (no atomics).
// ---------------------------------------------------------------------------
__global__ __launch_bounds__(C4) void copy_mean_kernel(
    const float4* __restrict__ x, float4* __restrict__ out4)
{
    int b     = blockIdx.x >> 4;
    int chunk = blockIdx.x & 15;
    int c4    = threadIdx.x;                         // 0..191

    size_t xbase = ((size_t)b * N + (size_t)chunk * TOKPC) * C4 + c4;
    size_t obase = ((size_t)b * NOUT + 2 * LEN + (size_t)chunk * TOKPC) * C4 + c4;

    float ax = 0.f, ay = 0.f, az = 0.f, aw = 0.f;
#pragma unroll 8
    for (int t = 0; t < TOKPC; ++t) {
        float4 v = x[xbase + (size_t)t * C4];
        out4[obase + (size_t)t * C4] = v;
        ax += v.x; ay += v.y; az += v.z; aw += v.w;
    }
    g_part[(b * NCHUNK + chunk) * C4 + c4] = make_float4(ax, ay, az, aw);
}

// ---------------------------------------------------------------------------
// 2) x_norm = l2norm(mean over tokens), written TRANSPOSED [c][b].
//    grid=B, block=192 (one float4 of channels per thread).
// ---------------------------------------------------------------------------
__global__ __launch_bounds__(C4) void xnorm_kernel() {
    __shared__ float sh[8];
    int b = blockIdx.x, c4 = threadIdx.x;
    float sx = 0.f, sy = 0.f, sz = 0.f, sw = 0.f;
#pragma unroll
    for (int k = 0; k < NCHUNK; ++k) {
        float4 p = g_part[(b * NCHUNK + k) * C4 + c4];
        sx += p.x; sy += p.y; sz += p.z; sw += p.w;
    }
    const float invN = 1.0f / (float)N;
    sx *= invN; sy *= invN; sz *= invN; sw *= invN;
    float ss = sx * sx + sy * sy + sz * sz + sw * sw;
#pragma unroll
    for (int o = 16; o > 0; o >>= 1) ss += __shfl_down_sync(0xffffffffu, ss, o);
    int warp = threadIdx.x >> 5, lane = threadIdx.x & 31;
    if (lane == 0) sh[warp] = ss;
    __syncthreads();
    if (threadIdx.x == 0) {
        float tot = sh[0] + sh[1] + sh[2] + sh[3] + sh[4] + sh[5];
        sh[0] = rsqrtf(fmaxf(tot, 1e-12f));
    }
    __syncthreads();
    float inv = sh[0];
    int c = c4 * 4;
    g_xnormT[(c + 0) * B + b] = sx * inv;
    g_xnormT[(c + 1) * B + b] = sy * inv;
    g_xnormT[(c + 2) * B + b] = sz * inv;
    g_xnormT[(c + 3) * B + b] = sw * inv;
}

// ---------------------------------------------------------------------------
// 3) inverse norms of both key pools   grid=2*POOL, block=256
// ---------------------------------------------------------------------------
__global__ void keynorm_kernel(const float* __restrict__ pk,
                               const float* __restrict__ rpk)
{
    __shared__ float sh[8];
    int p = blockIdx.x;
    const float* src = (p < POOL) ? (pk + (size_t)p * DIM)
                                  : (rpk + (size_t)(p - POOL) * DIM);
    float ss = 0.f;
#pragma unroll
    for (int i = 0; i < 3; ++i) {
        float v = src[threadIdx.x + i * 256];
        ss += v * v;
    }
#pragma unroll
    for (int o = 16; o > 0; o >>= 1) ss += __shfl_down_sync(0xffffffffu, ss, o);
    int warp = threadIdx.x >> 5, lane = threadIdx.x & 31;
    if (lane == 0) sh[warp] = ss;
    __syncthreads();
    if (threadIdx.x == 0) {
        float tot = 0.f;
#pragma unroll
        for (int w = 0; w < 8; ++w) tot += sh[w];
        float inv = rsqrtf(fmaxf(tot, 1e-12f));
        if (p < POOL) g_invn_key[p] = inv;
        else          g_invn_res[p - POOL] = inv;
    }
}

// ---------------------------------------------------------------------------
// 4) simT[p][b] = dot(vec[b], key[p]) * invn[p]
//    Output-stationary: thread owns (p, b0..b0+3) as one float4 accumulator.
//    No smem, no shuffles, no syncs. grid = POOL/SIMP = 128, block = 128.
//    Lanes 0-15 share p, cover all 64 b (coalesced 256B xT reads);
//    key float4 is warp-broadcast via L1.
// ---------------------------------------------------------------------------
template <int STAGE>
__global__ __launch_bounds__(128) void sim_kernel(const float* __restrict__ keys)
{
    const float* vecT = STAGE ? g_residT   : g_xnormT;   // [DIM][B]
    const float* invn = STAGE ? g_invn_res : g_invn_key;
    float*       simT = STAGE ? g_rsimT    : g_simT;     // [POOL][B]

    int p  = blockIdx.x * SIMP + (threadIdx.x >> 4);
    int b0 = (threadIdx.x & 15) * 4;

    const float4* kp = (const float4*)(keys + (size_t)p * DIM);
    float4 acc = make_float4(0.f, 0.f, 0.f, 0.f);

#pragma unroll 4
    for (int k4 = 0; k4 < C4; ++k4) {
        float4 kv = __ldg(kp + k4);
        const float* xb = vecT + (k4 * 4) * B + b0;
        float4 x0 = *(const float4*)(xb);
        float4 x1 = *(const float4*)(xb + B);
        float4 x2 = *(const float4*)(xb + 2 * B);
        float4 x3 = *(const float4*)(xb + 3 * B);
        acc.x += x0.x * kv.x; acc.y += x0.y * kv.x;
        acc.z += x0.z * kv.x; acc.w += x0.w * kv.x;
        acc.x += x1.x * kv.y; acc.y += x1.y * kv.y;
        acc.z += x1.z * kv.y; acc.w += x1.w * kv.y;
        acc.x += x2.x * kv.z; acc.y += x2.y * kv.z;
        acc.z += x2.z * kv.z; acc.w += x2.w * kv.z;
        acc.x += x3.x * kv.w; acc.y += x3.y * kv.w;
        acc.z += x3.z * kv.w; acc.w += x3.w * kv.w;
    }
    float inv = invn[p];
    acc.x *= inv; acc.y *= inv; acc.z *= inv; acc.w *= inv;
    *(float4*)(simT + (size_t)p * B + b0) = acc;
}

// ---------------------------------------------------------------------------
// 5) argmax over p (lowest index wins ties). STAGE 0 also builds residT.
//    grid=B, block=256
// ---------------------------------------------------------------------------
template <int STAGE>
__global__ void argmax_kernel(const float* __restrict__ pk)
{
    const float* simT = STAGE ? g_rsimT : g_simT;
    __shared__ float sv[256];
    __shared__ int   si[256];
    int b = blockIdx.x, tid = threadIdx.x;
    float best = -3.402823466e38f;
    int bi = 0x7fffffff;
#pragma unroll
    for (int i = 0; i < POOL / 256; ++i) {
        int p = tid + i * 256;
        float v = simT[(size_t)p * B + b];
        if (v > best || (v == best && p < bi)) { best = v; bi = p; }
    }
    sv[tid] = best; si[tid] = bi;
    __syncthreads();
    for (int s = 128; s > 0; s >>= 1) {
        if (tid < s) {
            float v = sv[tid + s]; int i2 = si[tid + s];
            if (v > sv[tid] || (v == sv[tid] && i2 < si[tid])) {
                sv[tid] = v; si[tid] = i2;
            }
        }
        __syncthreads();
    }
    if (tid == 0) {
        if (STAGE) { g_idx2[b] = si[0]; g_best2[b] = sv[0]; }
        else       { g_idx1[b] = si[0]; g_best1[b] = sv[0]; }
    }
    if (!STAGE) {
        __syncthreads();
        int idx = si[0];
#pragma unroll
        for (int i = 0; i < 3; ++i) {
            int c = tid + i * 256;
            g_residT[c * B + b] = pk[(size_t)idx * DIM + c] - g_xnormT[c * B + b];
        }
    }
}

// ---------------------------------------------------------------------------
// 6) gather selected prompts into out rows [0,32); last block writes scalar.
//    grid = 2*B + 1
//    which=0 -> residual_prompt[g_idx2] @ rows [0,16)
//    which=1 -> prompt[g_idx1]          @ rows [16,32)
// ---------------------------------------------------------------------------
__global__ __launch_bounds__(256) void gather_scalar_kernel(
    const float4* __restrict__ prompt4,
    const float4* __restrict__ rprompt4,
    float4* __restrict__ out4,
    float* __restrict__ out_scalar,
    int write_scalar)
{
    if (blockIdx.x == 2 * B) {
        if (!write_scalar || threadIdx.x >= 64) return;
        __shared__ float sh[2];
        float v = g_best1[threadIdx.x] + g_best2[threadIdx.x];
#pragma unroll
        for (int o = 16; o > 0; o >>= 1) v += __shfl_down_sync(0xffffffffu, v, o);
        if ((threadIdx.x & 31) == 0) sh[threadIdx.x >> 5] = v;
        __syncwarp();
        if (threadIdx.x == 0) {
            // both warps' partials: warp1 lane0 wrote sh[1]; need cross-warp sync
        }
        __syncthreads();
        if (threadIdx.x == 0)
            out_scalar[SCALAR_OFF] = (sh[0] + sh[1]) * (1.0f / (float)B);
        return;
    }
    int b = blockIdx.x >> 1;
    int which = blockIdx.x & 1;
    int idx = which ? g_idx1[b] : g_idx2[b];
    const float4* src = (which ? prompt4 : rprompt4) + (size_t)idx * LEN * C4;
    float4* dst = out4 + ((size_t)b * NOUT + (which ? LEN : 0)) * C4;
    for (int i = threadIdx.x; i < LEN * C4; i += 256)
        dst[i] = src[i];
}

// ---------------------------------------------------------------------------
// launch
// ---------------------------------------------------------------------------
extern "C" void kernel_launch(void* const* d_in, const int* in_sizes, int n_in,
                              void* d_out, int out_size)
{
    // Map inputs by element count (order-robust).
    const float* x_embed = nullptr;
    const float* prompt = nullptr, * rprompt = nullptr;
    const float* pkey = nullptr, * rpkey = nullptr;
    for (int i = 0; i < n_in; ++i) {
        int sz = in_sizes[i];
        if (sz == B * N * DIM) x_embed = (const float*)d_in[i];
        else if (sz == POOL * LEN * DIM) {
            if (!prompt) prompt = (const float*)d_in[i];
            else if (!rprompt) rprompt = (const float*)d_in[i];
        } else if (sz == POOL * DIM) {
            if (!pkey) pkey = (const float*)d_in[i];
            else if (!rpkey) rpkey = (const float*)d_in[i];
        }
    }
    float* out = (float*)d_out;

    copy_mean_kernel<<<B * NCHUNK, C4>>>((const float4*)x_embed, (float4*)out);
    xnorm_kernel<<<B, C4>>>();
    keynorm_kernel<<<2 * POOL, 256>>>(pkey, rpkey);
    sim_kernel<0><<<POOL / SIMP, 128>>>(pkey);
    argmax_kernel<0><<<B, 256>>>(pkey);
    sim_kernel<1><<<POOL / SIMP, 128>>>(rpkey);
    argmax_kernel<1><<<B, 256>>>(rpkey);
    int write_scalar = ((size_t)out_size > SCALAR_OFF) ? 1 : 0;
    gather_scalar_kernel<<<2 * B + 1, 256>>>(
        (const float4*)prompt, (const float4*)rprompt, (float4*)out,
        out, write_scalar);
}

// round 5
// speedup vs baseline: 1.3133x; 1.2099x over previous
#include <cuda_runtime.h>
#include <cstdint>

// ---------------------------------------------------------------------------
// Problem constants
// ---------------------------------------------------------------------------
#define B 64
#define N 2048
#define DIM 768
#define POOL 1024
#define LEN 16
#define NOUT 2080                 // 2*LEN + N
#define C4 (DIM / 4)              // 192 float4 per row
#define NCHUNK 16
#define TOKPC (N / NCHUNK)        // 128
#define SCALAR_OFF ((size_t)B * NOUT * DIM)

// ---------------------------------------------------------------------------
// Device scratch (no allocations). Only touched from device code — passing
// these symbols from host binds the host shadow copy (ATS trap).
// ---------------------------------------------------------------------------
__device__ __align__(16) float4 g_part[B * NCHUNK * C4];  // per-(b,chunk) sums
__device__ __align__(16) float  g_xnormT[DIM * B];        // x_norm^T [c][b]
__device__ __align__(16) float  g_residT[DIM * B];        // residual^T [c][b]
__device__ __align__(16) float  g_simT[POOL * B];         // sim^T [p][b]
__device__ __align__(16) float  g_rsimT[POOL * B];
__device__ float  g_invn_key[POOL];
__device__ float  g_invn_res[POOL];
__device__ int    g_idx1[B];
__device__ int    g_idx2[B];
__device__ float  g_best1[B];
__device__ float  g_best2[B];

// ---------------------------------------------------------------------------
// 1) Fused: copy x_embed -> out rows [32,2080) AND per-(b,chunk,c) sums.
//    grid = B*16, block = 192. Deterministic (no atomics).
// ---------------------------------------------------------------------------
__global__ __launch_bounds__(C4) void copy_mean_kernel(
    const float4* __restrict__ x, float4* __restrict__ out4)
{
    int b     = blockIdx.x >> 4;
    int chunk = blockIdx.x & 15;
    int c4    = threadIdx.x;                         // 0..191

    size_t xbase = ((size_t)b * N + (size_t)chunk * TOKPC) * C4 + c4;
    size_t obase = ((size_t)b * NOUT + 2 * LEN + (size_t)chunk * TOKPC) * C4 + c4;

    float ax = 0.f, ay = 0.f, az = 0.f, aw = 0.f;
#pragma unroll 8
    for (int t = 0; t < TOKPC; ++t) {
        float4 v = x[xbase + (size_t)t * C4];
        out4[obase + (size_t)t * C4] = v;
        ax += v.x; ay += v.y; az += v.z; aw += v.w;
    }
    g_part[(b * NCHUNK + chunk) * C4 + c4] = make_float4(ax, ay, az, aw);
}

// ---------------------------------------------------------------------------
// 2) Fused norms kernel.
//    blocks [0,B):          x_norm = l2norm(mean) -> g_xnormT (transposed)
//    blocks [B, B+2*POOL):  inverse norms of both key pools
//    block = 256
// ---------------------------------------------------------------------------
__global__ __launch_bounds__(256) void norms_kernel(
    const float* __restrict__ pk, const float* __restrict__ rpk)
{
    __shared__ float sh[8];
    int tid = threadIdx.x;
    int warp = tid >> 5, lane = tid & 31;

    if (blockIdx.x < B) {
        // ---- x_norm for batch b (threads 0..191 active for data) ----
        int b = blockIdx.x;
        int c4 = tid;
        float sx = 0.f, sy = 0.f, sz = 0.f, sw = 0.f;
        if (c4 < C4) {
#pragma unroll
            for (int k = 0; k < NCHUNK; ++k) {
                float4 p = g_part[(b * NCHUNK + k) * C4 + c4];
                sx += p.x; sy += p.y; sz += p.z; sw += p.w;
            }
            const float invN = 1.0f / (float)N;
            sx *= invN; sy *= invN; sz *= invN; sw *= invN;
        }
        float ss = sx * sx + sy * sy + sz * sz + sw * sw;
#pragma unroll
        for (int o = 16; o > 0; o >>= 1) ss += __shfl_down_sync(0xffffffffu, ss, o);
        if (lane == 0) sh[warp] = ss;
        __syncthreads();
        if (tid == 0) {
            float tot = 0.f;
#pragma unroll
            for (int w = 0; w < 8; ++w) tot += sh[w];
            sh[0] = rsqrtf(fmaxf(tot, 1e-12f));
        }
        __syncthreads();
        if (c4 < C4) {
            float inv = sh[0];
            int c = c4 * 4;
            g_xnormT[(c + 0) * B + b] = sx * inv;
            g_xnormT[(c + 1) * B + b] = sy * inv;
            g_xnormT[(c + 2) * B + b] = sz * inv;
            g_xnormT[(c + 3) * B + b] = sw * inv;
        }
    } else {
        // ---- key-pool inverse norms ----
        int p = blockIdx.x - B;
        const float* src = (p < POOL) ? (pk + (size_t)p * DIM)
                                      : (rpk + (size_t)(p - POOL) * DIM);
        float ss = 0.f;
#pragma unroll
        for (int i = 0; i < 3; ++i) {
            float v = src[tid + i * 256];
            ss += v * v;
        }
#pragma unroll
        for (int o = 16; o > 0; o >>= 1) ss += __shfl_down_sync(0xffffffffu, ss, o);
        if (lane == 0) sh[warp] = ss;
        __syncthreads();
        if (tid == 0) {
            float tot = 0.f;
#pragma unroll
            for (int w = 0; w < 8; ++w) tot += sh[w];
            float inv = rsqrtf(fmaxf(tot, 1e-12f));
            if (p < POOL) g_invn_key[p] = inv;
            else          g_invn_res[p - POOL] = inv;
        }
    }
}

// ---------------------------------------------------------------------------
// 3) simT[p][b] = dot(vec[b], key[p]) * invn[p]
//    ONE WARP PER POOL ROW p; lane owns batches (2*lane, 2*lane+1) as float2.
//    Per k: 1 coalesced 256B float2 x-load + 1 warp-uniform key load + 2 FMA.
//    grid = 256 blocks x 128 threads = 1024 warps (~7/SM on all 148 SMs).
// ---------------------------------------------------------------------------
template <int STAGE>
__global__ __launch_bounds__(128) void sim_kernel(const float* __restrict__ keys)
{
    const float* vecT = STAGE ? g_residT   : g_xnormT;   // [DIM][B]
    const float* invn = STAGE ? g_invn_res : g_invn_key;
    float*       simT = STAGE ? g_rsimT    : g_simT;     // [POOL][B]

    int p    = blockIdx.x * 4 + (threadIdx.x >> 5);      // 0..1023
    int lane = threadIdx.x & 31;

    const float*  kp = keys + (size_t)p * DIM;
    const float2* xv = (const float2*)(vecT) + lane;     // stride B/2 float2

    float ax = 0.f, ay = 0.f;
#pragma unroll 8
    for (int k = 0; k < DIM; ++k) {
        float kv = __ldg(kp + k);
        float2 x = xv[(size_t)k * (B / 2)];
        ax += kv * x.x;
        ay += kv * x.y;
    }
    float inv = invn[p];
    ((float2*)(simT + (size_t)p * B))[lane] = make_float2(ax * inv, ay * inv);
}

// ---------------------------------------------------------------------------
// 4) argmax over p (lowest index wins ties). STAGE 0 also builds residT.
//    grid=B, block=256
// ---------------------------------------------------------------------------
template <int STAGE>
__global__ void argmax_kernel(const float* __restrict__ pk)
{
    const float* simT = STAGE ? g_rsimT : g_simT;
    __shared__ float sv[256];
    __shared__ int   si[256];
    int b = blockIdx.x, tid = threadIdx.x;
    float best = -3.402823466e38f;
    int bi = 0x7fffffff;
#pragma unroll
    for (int i = 0; i < POOL / 256; ++i) {
        int p = tid + i * 256;
        float v = simT[(size_t)p * B + b];
        if (v > best || (v == best && p < bi)) { best = v; bi = p; }
    }
    sv[tid] = best; si[tid] = bi;
    __syncthreads();
    for (int s = 128; s > 0; s >>= 1) {
        if (tid < s) {
            float v = sv[tid + s]; int i2 = si[tid + s];
            if (v > sv[tid] || (v == sv[tid] && i2 < si[tid])) {
                sv[tid] = v; si[tid] = i2;
            }
        }
        __syncthreads();
    }
    if (tid == 0) {
        if (STAGE) { g_idx2[b] = si[0]; g_best2[b] = sv[0]; }
        else       { g_idx1[b] = si[0]; g_best1[b] = sv[0]; }
    }
    if (!STAGE) {
        __syncthreads();
        int idx = si[0];
#pragma unroll
        for (int i = 0; i < 3; ++i) {
            int c = tid + i * 256;
            g_residT[c * B + b] = pk[(size_t)idx * DIM + c] - g_xnormT[c * B + b];
        }
    }
}

// ---------------------------------------------------------------------------
// 5) gather selected prompts into out rows [0,32); last block writes scalar.
//    grid = 2*B + 1
//    which=0 -> residual_prompt[g_idx2] @ rows [0,16)
//    which=1 -> prompt[g_idx1]          @ rows [16,32)
// ---------------------------------------------------------------------------
__global__ __launch_bounds__(256) void gather_scalar_kernel(
    const float4* __restrict__ prompt4,
    const float4* __restrict__ rprompt4,
    float4* __restrict__ out4,
    float* __restrict__ out_scalar,
    int write_scalar)
{
    if (blockIdx.x == 2 * B) {
        __shared__ float sh[2];
        if (write_scalar && threadIdx.x < 64) {
            float v = g_best1[threadIdx.x] + g_best2[threadIdx.x];
#pragma unroll
            for (int o = 16; o > 0; o >>= 1)
                v += __shfl_down_sync(0xffffffffu, v, o);
            if ((threadIdx.x & 31) == 0) sh[threadIdx.x >> 5] = v;
        }
        __syncthreads();
        if (write_scalar && threadIdx.x == 0)
            out_scalar[SCALAR_OFF] = (sh[0] + sh[1]) * (1.0f / (float)B);
        return;
    }
    int b = blockIdx.x >> 1;
    int which = blockIdx.x & 1;
    int idx = which ? g_idx1[b] : g_idx2[b];
    const float4* src = (which ? prompt4 : rprompt4) + (size_t)idx * LEN * C4;
    float4* dst = out4 + ((size_t)b * NOUT + (which ? LEN : 0)) * C4;
    for (int i = threadIdx.x; i < LEN * C4; i += 256)
        dst[i] = src[i];
}

// ---------------------------------------------------------------------------
// launch
// ---------------------------------------------------------------------------
extern "C" void kernel_launch(void* const* d_in, const int* in_sizes, int n_in,
                              void* d_out, int out_size)
{
    // Map inputs by element count (order-robust).
    const float* x_embed = nullptr;
    const float* prompt = nullptr, * rprompt = nullptr;
    const float* pkey = nullptr, * rpkey = nullptr;
    for (int i = 0; i < n_in; ++i) {
        int sz = in_sizes[i];
        if (sz == B * N * DIM) x_embed = (const float*)d_in[i];
        else if (sz == POOL * LEN * DIM) {
            if (!prompt) prompt = (const float*)d_in[i];
            else if (!rprompt) rprompt = (const float*)d_in[i];
        } else if (sz == POOL * DIM) {
            if (!pkey) pkey = (const float*)d_in[i];
            else if (!rpkey) rpkey = (const float*)d_in[i];
        }
    }
    float* out = (float*)d_out;

    copy_mean_kernel<<<B * NCHUNK, C4>>>((const float4*)x_embed, (float4*)out);
    norms_kernel<<<B + 2 * POOL, 256>>>(pkey, rpkey);
    sim_kernel<0><<<POOL / 4, 128>>>(pkey);
    argmax_kernel<0><<<B, 256>>>(pkey);
    sim_kernel<1><<<POOL / 4, 128>>>(rpkey);
    argmax_kernel<1><<<B, 256>>>(rpkey);
    int write_scalar = ((size_t)out_size > SCALAR_OFF) ? 1 : 0;
    gather_scalar_kernel<<<2 * B + 1, 256>>>(
        (const float4*)prompt, (const float4*)rprompt, (float4*)out,
        out, write_scalar);
}

// round 7
// speedup vs baseline: 1.7665x; 1.3451x over previous
#include <cuda_runtime.h>
#include <cstdint>

// ---------------------------------------------------------------------------
// Problem constants
// ---------------------------------------------------------------------------
#define B 64
#define N 2048
#define DIM 768
#define POOL 1024
#define LEN 16
#define NOUT 2080                 // 2*LEN + N
#define C4 (DIM / 4)              // 192 float4 per row
#define NCHUNK 32
#define TOKPC (N / NCHUNK)        // 64
#define SCALAR_OFF ((size_t)B * NOUT * DIM)
#define KSTRIPE (DIM / 8)         // 96 k's per warp in sim

// ---------------------------------------------------------------------------
// Device scratch (no allocations). Only touched from device code — passing
// these symbols from host binds the host shadow copy (ATS trap).
// ---------------------------------------------------------------------------
__device__ __align__(16) float4 g_part[B * NCHUNK * C4];  // per-(b,chunk) sums
__device__ __align__(16) float  g_xnormT[DIM * B];        // x_norm^T [c][b]
__device__ __align__(16) float  g_residT[DIM * B];        // residual^T [c][b]
__device__ __align__(16) float  g_simT[POOL * B];         // sim^T [p][b]
__device__ __align__(16) float  g_rsimT[POOL * B];
__device__ float  g_invn_key[POOL];
__device__ float  g_invn_res[POOL];
__device__ int    g_idx1[B];
__device__ int    g_idx2[B];
__device__ float  g_best1[B];
__device__ float  g_best2[B];

// ---------------------------------------------------------------------------
// 1) Fused: copy x_embed -> out rows [32,2080) AND per-(b,chunk,c) sums.
//    grid = B*32 = 2048, block = 192. Deterministic (no atomics).
// ---------------------------------------------------------------------------
__global__ __launch_bounds__(C4) void copy_mean_kernel(
    const float4* __restrict__ x, float4* __restrict__ out4)
{
    int b     = blockIdx.x >> 5;
    int chunk = blockIdx.x & 31;
    int c4    = threadIdx.x;                         // 0..191

    size_t xbase = ((size_t)b * N + (size_t)chunk * TOKPC) * C4 + c4;
    size_t obase = ((size_t)b * NOUT + 2 * LEN + (size_t)chunk * TOKPC) * C4 + c4;

    float ax = 0.f, ay = 0.f, az = 0.f, aw = 0.f;
#pragma unroll 8
    for (int t = 0; t < TOKPC; ++t) {
        float4 v = x[xbase + (size_t)t * C4];
        out4[obase + (size_t)t * C4] = v;
        ax += v.x; ay += v.y; az += v.z; aw += v.w;
    }
    g_part[(b * NCHUNK + chunk) * C4 + c4] = make_float4(ax, ay, az, aw);
}

// ---------------------------------------------------------------------------
// 2) Fused norms kernel.
//    blocks [0,B):          x_norm = l2norm(mean) -> g_xnormT (transposed)
//    blocks [B, B+2*POOL):  inverse norms of both key pools
//    block = 256
// ---------------------------------------------------------------------------
__global__ __launch_bounds__(256) void norms_kernel(
    const float* __restrict__ pk, const float* __restrict__ rpk)
{
    __shared__ float sh[8];
    int tid = threadIdx.x;
    int warp = tid >> 5, lane = tid & 31;

    if (blockIdx.x < B) {
        int b = blockIdx.x;
        int c4 = tid;
        float sx = 0.f, sy = 0.f, sz = 0.f, sw = 0.f;
        if (c4 < C4) {
#pragma unroll
            for (int k = 0; k < NCHUNK; ++k) {
                float4 p = g_part[(b * NCHUNK + k) * C4 + c4];
                sx += p.x; sy += p.y; sz += p.z; sw += p.w;
            }
            const float invN = 1.0f / (float)N;
            sx *= invN; sy *= invN; sz *= invN; sw *= invN;
        }
        float ss = sx * sx + sy * sy + sz * sz + sw * sw;
#pragma unroll
        for (int o = 16; o > 0; o >>= 1) ss += __shfl_down_sync(0xffffffffu, ss, o);
        if (lane == 0) sh[warp] = ss;
        __syncthreads();
        if (tid == 0) {
            float tot = 0.f;
#pragma unroll
            for (int w = 0; w < 8; ++w) tot += sh[w];
            sh[0] = rsqrtf(fmaxf(tot, 1e-12f));
        }
        __syncthreads();
        if (c4 < C4) {
            float inv = sh[0];
            int c = c4 * 4;
            g_xnormT[(c + 0) * B + b] = sx * inv;
            g_xnormT[(c + 1) * B + b] = sy * inv;
            g_xnormT[(c + 2) * B + b] = sz * inv;
            g_xnormT[(c + 3) * B + b] = sw * inv;
        }
    } else {
        int p = blockIdx.x - B;
        const float* src = (p < POOL) ? (pk + (size_t)p * DIM)
                                      : (rpk + (size_t)(p - POOL) * DIM);
        float ss = 0.f;
#pragma unroll
        for (int i = 0; i < 3; ++i) {
            float v = src[tid + i * 256];
            ss += v * v;
        }
#pragma unroll
        for (int o = 16; o > 0; o >>= 1) ss += __shfl_down_sync(0xffffffffu, ss, o);
        if (lane == 0) sh[warp] = ss;
        __syncthreads();
        if (tid == 0) {
            float tot = 0.f;
#pragma unroll
            for (int w = 0; w < 8; ++w) tot += sh[w];
            float inv = rsqrtf(fmaxf(tot, 1e-12f));
            if (p < POOL) g_invn_key[p] = inv;
            else          g_invn_res[p - POOL] = inv;
        }
    }
}

// ---------------------------------------------------------------------------
// 3) simT[p][b] = dot(vec[b], key[p]) * invn[p]
//    Block handles 2 pool rows; 8 warps split k into 96-wide stripes;
//    lane owns batch pair (2*lane, 2*lane+1). One x-load feeds 2 keys
//    (4 FMA / 8B). Cross-warp reduce in smem, warp 0 writes.
//    grid = POOL/2 = 512, block = 256 -> ~28 warps/SM on all SMs.
// ---------------------------------------------------------------------------
template <int STAGE>
__global__ __launch_bounds__(256) void sim_kernel(const float* __restrict__ keys)
{
    const float* vecT = STAGE ? g_residT   : g_xnormT;   // [DIM][B]
    const float* invn = STAGE ? g_invn_res : g_invn_key;
    float*       simT = STAGE ? g_rsimT    : g_simT;     // [POOL][B]

    int p0   = blockIdx.x * 2;
    int warp = threadIdx.x >> 5, lane = threadIdx.x & 31;

    const float*  k0p = keys + (size_t)p0 * DIM;
    const float*  k1p = k0p + DIM;
    const float2* xv  = (const float2*)vecT + lane;      // +k*(B/2)

    float a0x = 0.f, a0y = 0.f, a1x = 0.f, a1y = 0.f;
    int kb = warp * KSTRIPE;
#pragma unroll 8
    for (int i = 0; i < KSTRIPE; ++i) {
        int k = kb + i;
        float  kv0 = __ldg(k0p + k);
        float  kv1 = __ldg(k1p + k);
        float2 x   = xv[(size_t)k * (B / 2)];
        a0x += kv0 * x.x; a0y += kv0 * x.y;
        a1x += kv1 * x.x; a1y += kv1 * x.y;
    }
    __shared__ float4 spart[8][32];
    spart[warp][lane] = make_float4(a0x, a0y, a1x, a1y);
    __syncthreads();
    if (warp == 0) {
        float sx = 0.f, sy = 0.f, tx = 0.f, ty = 0.f;
#pragma unroll
        for (int w = 0; w < 8; ++w) {
            float4 v = spart[w][lane];
            sx += v.x; sy += v.y; tx += v.z; ty += v.w;
        }
        float i0 = invn[p0], i1 = invn[p0 + 1];
        ((float2*)(simT + (size_t)p0 * B))[lane]       = make_float2(sx * i0, sy * i0);
        ((float2*)(simT + (size_t)(p0 + 1) * B))[lane] = make_float2(tx * i1, ty * i1);
    }
}

// ---------------------------------------------------------------------------
// 4) argmax over p (lowest index wins ties), coalesced.
//    grid = 2 blocks x 1024 threads. Block handles 32 batches.
//    Warp w scans p-stripe [w*32, w*32+32); lane owns batch b0+lane
//    (loads are 128B coalesced). 32x32 smem transpose, then warp j
//    shuffle-reduces batch j across the 32 warp-candidates.
//    STAGE 0 additionally builds residT (coalesced writes).
// ---------------------------------------------------------------------------
template <int STAGE>
__global__ __launch_bounds__(1024) void argmax_kernel(const float* __restrict__ pk)
{
    const float* simT = STAGE ? g_rsimT : g_simT;
    int b0   = blockIdx.x * 32;
    int warp = threadIdx.x >> 5, lane = threadIdx.x & 31;
    int b    = b0 + lane;

    float best = -3.402823466e38f;
    int   bi   = 0;
#pragma unroll
    for (int i = 0; i < 32; ++i) {
        int p = warp * 32 + i;                       // increasing p
        float v = simT[(size_t)p * B + b];
        if (v > best) { best = v; bi = p; }          // strict > keeps lowest p
    }

    __shared__ float sv[32][33];
    __shared__ int   si[32][33];
    __shared__ int   sidx[32];
    sv[warp][lane] = best; si[warp][lane] = bi;
    __syncthreads();

    // warp j reduces batch j: lane w holds warp w's candidate for batch j
    float v  = sv[lane][warp];
    int   id = si[lane][warp];
#pragma unroll
    for (int o = 16; o > 0; o >>= 1) {
        float vo = __shfl_down_sync(0xffffffffu, v, o);
        int   io = __shfl_down_sync(0xffffffffu, id, o);
        if (vo > v || (vo == v && io < id)) { v = vo; id = io; }
    }
    if (lane == 0) {
        int bb = b0 + warp;
        if (STAGE) { g_idx2[bb] = id; g_best2[bb] = v; }
        else       { g_idx1[bb] = id; g_best1[bb] = v; sidx[warp] = id; }
    }
    if (!STAGE) {
        __syncthreads();
        // residT[c][b0+bl] = pk[idx[bl]][c] - xnormT[c][b0+bl]
        for (int i = threadIdx.x; i < 32 * DIM; i += 1024) {
            int c  = i >> 5;
            int bl = i & 31;
            int id2 = sidx[bl];
            g_residT[c * B + b0 + bl] =
                pk[(size_t)id2 * DIM + c] - g_xnormT[c * B + b0 + bl];
        }
    }
}

// ---------------------------------------------------------------------------
// 5) gather selected prompts into out rows [0,32); last block writes scalar.
//    grid = 2*B + 1
//    which=0 -> residual_prompt[g_idx2] @ rows [0,16)
//    which=1 -> prompt[g_idx1]          @ rows [16,32)
// ---------------------------------------------------------------------------
__global__ __launch_bounds__(256) void gather_scalar_kernel(
    const float4* __restrict__ prompt4,
    const float4* __restrict__ rprompt4,
    float4* __restrict__ out4,
    float* __restrict__ out_scalar,
    int write_scalar)
{
    if (blockIdx.x == 2 * B) {
        __shared__ float sh[2];
        if (write_scalar && threadIdx.x < 64) {
            float v = g_best1[threadIdx.x] + g_best2[threadIdx.x];
#pragma unroll
            for (int o = 16; o > 0; o >>= 1)
                v += __shfl_down_sync(0xffffffffu, v, o);
            if ((threadIdx.x & 31) == 0) sh[threadIdx.x >> 5] = v;
        }
        __syncthreads();
        if (write_scalar && threadIdx.x == 0)
            out_scalar[SCALAR_OFF] = (sh[0] + sh[1]) * (1.0f / (float)B);
        return;
    }
    int b = blockIdx.x >> 1;
    int which = blockIdx.x & 1;
    int idx = which ? g_idx1[b] : g_idx2[b];
    const float4* src = (which ? prompt4 : rprompt4) + (size_t)idx * LEN * C4;
    float4* dst = out4 + ((size_t)b * NOUT + (which ? LEN : 0)) * C4;
    for (int i = threadIdx.x; i < LEN * C4; i += 256)
        dst[i] = src[i];
}

// ---------------------------------------------------------------------------
// launch
// ---------------------------------------------------------------------------
extern "C" void kernel_launch(void* const* d_in, const int* in_sizes, int n_in,
                              void* d_out, int out_size)
{
    // Map inputs by element count (order-robust).
    const float* x_embed = nullptr;
    const float* prompt = nullptr, * rprompt = nullptr;
    const float* pkey = nullptr, * rpkey = nullptr;
    for (int i = 0; i < n_in; ++i) {
        int sz = in_sizes[i];
        if (sz == B * N * DIM) x_embed = (const float*)d_in[i];
        else if (sz == POOL * LEN * DIM) {
            if (!prompt) prompt = (const float*)d_in[i];
            else if (!rprompt) rprompt = (const float*)d_in[i];
        } else if (sz == POOL * DIM) {
            if (!pkey) pkey = (const float*)d_in[i];
            else if (!rpkey) rpkey = (const float*)d_in[i];
        }
    }
    float* out = (float*)d_out;

    copy_mean_kernel<<<B * NCHUNK, C4>>>((const float4*)x_embed, (float4*)out);
    norms_kernel<<<B + 2 * POOL, 256>>>(pkey, rpkey);
    sim_kernel<0><<<POOL / 2, 256>>>(pkey);
    argmax_kernel<0><<<2, 1024>>>(pkey);
    sim_kernel<1><<<POOL / 2, 256>>>(rpkey);
    argmax_kernel<1><<<2, 1024>>>(rpkey);
    int write_scalar = ((size_t)out_size > SCALAR_OFF) ? 1 : 0;
    gather_scalar_kernel<<<2 * B + 1, 256>>>(
        (const float4*)prompt, (const float4*)rprompt, (float4*)out,
        out, write_scalar);
}

// round 8
// speedup vs baseline: 1.9463x; 1.1018x over previous
#include <cuda_runtime.h>
#include <cstdint>

// ---------------------------------------------------------------------------
// Problem constants
// ---------------------------------------------------------------------------
#define B 64
#define N 2048
#define DIM 768
#define POOL 1024
#define LEN 16
#define NOUT 2080                 // 2*LEN + N
#define C4 (DIM / 4)              // 192 float4 per row
#define NCHUNK 32
#define TOKPC (N / NCHUNK)        // 64
#define SCALAR_OFF ((size_t)B * NOUT * DIM)
#define KSTRIPE (DIM / 8)         // 96 k's per warp in sim

// ---------------------------------------------------------------------------
// Device scratch (no allocations). Only touched from device code — passing
// these symbols from host binds the host shadow copy (ATS trap).
// ---------------------------------------------------------------------------
__device__ __align__(16) float4 g_part[B * NCHUNK * C4];  // per-(b,chunk) sums
__device__ __align__(16) float  g_xnormT[DIM * B];        // x_norm^T [c][b]
__device__ __align__(16) float  g_residT[DIM * B];        // residual^T [c][b]
__device__ __align__(16) float  g_sim[B * POOL];          // sim [b][p]
__device__ __align__(16) float  g_rsim[B * POOL];         // res-sim [b][p]
__device__ int    g_idx1[B];
__device__ int    g_idx2[B];
__device__ float  g_best1[B];
__device__ float  g_best2[B];

// ---------------------------------------------------------------------------
// 1) Fused: copy x_embed -> out rows [32,2080) AND per-(b,chunk,c) sums.
//    grid = B*32 = 2048, block = 192. Deterministic (no atomics).
// ---------------------------------------------------------------------------
__global__ __launch_bounds__(C4) void copy_mean_kernel(
    const float4* __restrict__ x, float4* __restrict__ out4)
{
    int b     = blockIdx.x >> 5;
    int chunk = blockIdx.x & 31;
    int c4    = threadIdx.x;                         // 0..191

    size_t xbase = ((size_t)b * N + (size_t)chunk * TOKPC) * C4 + c4;
    size_t obase = ((size_t)b * NOUT + 2 * LEN + (size_t)chunk * TOKPC) * C4 + c4;

    float ax = 0.f, ay = 0.f, az = 0.f, aw = 0.f;
#pragma unroll 8
    for (int t = 0; t < TOKPC; ++t) {
        float4 v = x[xbase + (size_t)t * C4];
        out4[obase + (size_t)t * C4] = v;
        ax += v.x; ay += v.y; az += v.z; aw += v.w;
    }
    g_part[(b * NCHUNK + chunk) * C4 + c4] = make_float4(ax, ay, az, aw);
}

// ---------------------------------------------------------------------------
// 2) x_norm = l2norm(mean) -> g_xnormT (transposed).  grid=B, block=256.
// ---------------------------------------------------------------------------
__global__ __launch_bounds__(256) void xnorm_kernel()
{
    __shared__ float sh[8];
    int tid = threadIdx.x;
    int warp = tid >> 5, lane = tid & 31;
    int b = blockIdx.x;
    int c4 = tid;
    float sx = 0.f, sy = 0.f, sz = 0.f, sw = 0.f;
    if (c4 < C4) {
#pragma unroll
        for (int k = 0; k < NCHUNK; ++k) {
            float4 p = g_part[(b * NCHUNK + k) * C4 + c4];
            sx += p.x; sy += p.y; sz += p.z; sw += p.w;
        }
        const float invN = 1.0f / (float)N;
        sx *= invN; sy *= invN; sz *= invN; sw *= invN;
    }
    float ss = sx * sx + sy * sy + sz * sz + sw * sw;
#pragma unroll
    for (int o = 16; o > 0; o >>= 1) ss += __shfl_down_sync(0xffffffffu, ss, o);
    if (lane == 0) sh[warp] = ss;
    __syncthreads();
    if (tid == 0) {
        float tot = 0.f;
#pragma unroll
        for (int w = 0; w < 8; ++w) tot += sh[w];
        sh[0] = rsqrtf(fmaxf(tot, 1e-12f));
    }
    __syncthreads();
    if (c4 < C4) {
        float inv = sh[0];
        int c = c4 * 4;
        g_xnormT[(c + 0) * B + b] = sx * inv;
        g_xnormT[(c + 1) * B + b] = sy * inv;
        g_xnormT[(c + 2) * B + b] = sz * inv;
        g_xnormT[(c + 3) * B + b] = sw * inv;
    }
}

// ---------------------------------------------------------------------------
// 3) sim[b][p] = dot(vec[b], key[p]) * rsqrt(max(||key[p]||^2, eps))
//    Key norms computed INLINE (key rows are streamed anyway; every lane
//    computes the same per-warp partial — free, no extra loads).
//    Block handles 2 pool rows; 8 warps split k; lane owns a batch pair.
//    grid = POOL/2 = 512, block = 256.
// ---------------------------------------------------------------------------
template <int STAGE>
__global__ __launch_bounds__(256) void sim_kernel(const float* __restrict__ keys)
{
    const float* vecT = STAGE ? g_residT : g_xnormT;   // [DIM][B]
    float*       simB = STAGE ? g_rsim   : g_sim;      // [B][POOL]

    int p0   = blockIdx.x * 2;
    int warp = threadIdx.x >> 5, lane = threadIdx.x & 31;

    const float*  k0p = keys + (size_t)p0 * DIM;
    const float*  k1p = k0p + DIM;
    const float2* xv  = (const float2*)vecT + lane;    // +k*(B/2)

    float a0x = 0.f, a0y = 0.f, a1x = 0.f, a1y = 0.f;
    float ss0 = 0.f, ss1 = 0.f;                        // identical across lanes
    int kb = warp * KSTRIPE;
#pragma unroll 8
    for (int i = 0; i < KSTRIPE; ++i) {
        int k = kb + i;
        float  kv0 = __ldg(k0p + k);
        float  kv1 = __ldg(k1p + k);
        ss0 += kv0 * kv0;
        ss1 += kv1 * kv1;
        float2 x = xv[(size_t)k * (B / 2)];
        a0x += kv0 * x.x; a0y += kv0 * x.y;
        a1x += kv1 * x.x; a1y += kv1 * x.y;
    }
    __shared__ float4 spart[8][32];
    __shared__ float2 snorm[8];
    spart[warp][lane] = make_float4(a0x, a0y, a1x, a1y);
    if (lane == 0) snorm[warp] = make_float2(ss0, ss1);
    __syncthreads();
    if (warp == 0) {
        float sx = 0.f, sy = 0.f, tx = 0.f, ty = 0.f;
        float n0 = 0.f, n1 = 0.f;
#pragma unroll
        for (int w = 0; w < 8; ++w) {
            float4 v = spart[w][lane];
            sx += v.x; sy += v.y; tx += v.z; ty += v.w;
            n0 += snorm[w].x; n1 += snorm[w].y;
        }
        float i0 = rsqrtf(fmaxf(n0, 1e-12f));
        float i1 = rsqrtf(fmaxf(n1, 1e-12f));
        int b0 = lane * 2;
        simB[(size_t)b0 * POOL + p0]           = sx * i0;
        simB[(size_t)(b0 + 1) * POOL + p0]     = sy * i0;
        simB[(size_t)b0 * POOL + p0 + 1]       = tx * i1;
        simB[(size_t)(b0 + 1) * POOL + p0 + 1] = ty * i1;
    }
}

// ---------------------------------------------------------------------------
// 4) argmax over p (lowest index wins ties) + fused gather (+residT on S0).
//    One block per batch; one float4 of sim row per thread (coalesced 4KB).
//    STAGE 0: writes idx1/best1, builds residT, copies prompt[idx1] to
//             out rows [16,32).
//    STAGE 1: writes idx2/best2, copies residual_prompt[idx2] to rows [0,16).
//    grid = B, block = 256.
// ---------------------------------------------------------------------------
template <int STAGE>
__global__ __launch_bounds__(256) void argmax_kernel(
    const float* __restrict__ pk,          // prompt_key (STAGE 0 only)
    const float4* __restrict__ gsrc,       // prompt(S0) / residual_prompt(S1)
    float4* __restrict__ out4)
{
    __shared__ float swv[8];
    __shared__ int   swi[8];
    __shared__ int   s_idx;
    int b = blockIdx.x, tid = threadIdx.x;
    int warp = tid >> 5, lane = tid & 31;

    const float* simRow = (STAGE ? g_rsim : g_sim) + (size_t)b * POOL;
    float4 v4 = ((const float4*)simRow)[tid];

    // in-thread: ascending p with strict > keeps lowest index on ties
    float best = v4.x; int bi = tid * 4;
    if (v4.y > best) { best = v4.y; bi = tid * 4 + 1; }
    if (v4.z > best) { best = v4.z; bi = tid * 4 + 2; }
    if (v4.w > best) { best = v4.w; bi = tid * 4 + 3; }

#pragma unroll
    for (int o = 16; o > 0; o >>= 1) {
        float vo = __shfl_down_sync(0xffffffffu, best, o);
        int   io = __shfl_down_sync(0xffffffffu, bi, o);
        if (vo > best || (vo == best && io < bi)) { best = vo; bi = io; }
    }
    if (lane == 0) { swv[warp] = best; swi[warp] = bi; }
    __syncthreads();
    if (tid == 0) {
        float v = swv[0]; int id = swi[0];
#pragma unroll
        for (int w = 1; w < 8; ++w) {
            if (swv[w] > v || (swv[w] == v && swi[w] < id)) {
                v = swv[w]; id = swi[w];
            }
        }
        s_idx = id;
        if (STAGE) { g_idx2[b] = id; g_best2[b] = v; }
        else       { g_idx1[b] = id; g_best1[b] = v; }
    }
    __syncthreads();
    int idx = s_idx;

    if (!STAGE) {
        // residT[c][b] = pk[idx][c] - xnormT[c][b]
#pragma unroll
        for (int i = 0; i < 3; ++i) {
            int c = tid + i * 256;
            g_residT[c * B + b] = pk[(size_t)idx * DIM + c] - g_xnormT[c * B + b];
        }
    }

    // fused gather: 16 rows of DIM floats = 3072 float4
    const float4* src = gsrc + (size_t)idx * LEN * C4;
    float4* dst = out4 + ((size_t)b * NOUT + (STAGE ? 0 : LEN)) * C4;
#pragma unroll
    for (int i = 0; i < LEN * C4 / 256; ++i)
        dst[tid + i * 256] = src[tid + i * 256];
}

// ---------------------------------------------------------------------------
// 5) scalar: (sum_b best1 + sum_b best2) / B   (1 block)
// ---------------------------------------------------------------------------
__global__ void scalar_kernel(float* __restrict__ out, int write) {
    if (!write) return;
    __shared__ float sh[2];
    float v = (threadIdx.x < B)
                  ? (g_best1[threadIdx.x] + g_best2[threadIdx.x]) : 0.0f;
#pragma unroll
    for (int o = 16; o > 0; o >>= 1) v += __shfl_down_sync(0xffffffffu, v, o);
    if ((threadIdx.x & 31) == 0) sh[threadIdx.x >> 5] = v;
    __syncthreads();
    if (threadIdx.x == 0) out[SCALAR_OFF] = (sh[0] + sh[1]) * (1.0f / (float)B);
}

// ---------------------------------------------------------------------------
// launch
// ---------------------------------------------------------------------------
extern "C" void kernel_launch(void* const* d_in, const int* in_sizes, int n_in,
                              void* d_out, int out_size)
{
    // Map inputs by element count (order-robust).
    const float* x_embed = nullptr;
    const float* prompt = nullptr, * rprompt = nullptr;
    const float* pkey = nullptr, * rpkey = nullptr;
    for (int i = 0; i < n_in; ++i) {
        int sz = in_sizes[i];
        if (sz == B * N * DIM) x_embed = (const float*)d_in[i];
        else if (sz == POOL * LEN * DIM) {
            if (!prompt) prompt = (const float*)d_in[i];
            else if (!rprompt) rprompt = (const float*)d_in[i];
        } else if (sz == POOL * DIM) {
            if (!pkey) pkey = (const float*)d_in[i];
            else if (!rpkey) rpkey = (const float*)d_in[i];
        }
    }
    float* out = (float*)d_out;

    copy_mean_kernel<<<B * NCHUNK, C4>>>((const float4*)x_embed, (float4*)out);
    xnorm_kernel<<<B, 256>>>();
    sim_kernel<0><<<POOL / 2, 256>>>(pkey);
    argmax_kernel<0><<<B, 256>>>(pkey, (const float4*)prompt, (float4*)out);
    sim_kernel<1><<<POOL / 2, 256>>>(rpkey);
    argmax_kernel<1><<<B, 256>>>(nullptr, (const float4*)rprompt, (float4*)out);
    int write_scalar = ((size_t)out_size > SCALAR_OFF) ? 1 : 0;
    scalar_kernel<<<1, 64>>>(out, write_scalar);
}

// round 9
// speedup vs baseline: 1.9695x; 1.0119x over previous
#include <cuda_runtime.h>
#include <cstdint>

// ---------------------------------------------------------------------------
// Problem constants
// ---------------------------------------------------------------------------
#define B 64
#define N 2048
#define DIM 768
#define POOL 1024
#define LEN 16
#define NOUT 2080                 // 2*LEN + N
#define C4 (DIM / 4)              // 192 float4 per row
#define NCHUNK 32
#define TOKPC (N / NCHUNK)        // 64
#define SCALAR_OFF ((size_t)B * NOUT * DIM)
#define KSTRIPE (DIM / 8)         // 96 k's per warp in sim

// ---------------------------------------------------------------------------
// Device scratch (no allocations). Only touched from device code — passing
// these symbols from host binds the host shadow copy (ATS trap).
// ---------------------------------------------------------------------------
__device__ __align__(16) float4 g_part[B * NCHUNK * C4];  // per-(b,chunk) sums
__device__ __align__(16) float  g_xnormT[DIM * B];        // x_norm^T [c][b]
__device__ __align__(16) float  g_residT[DIM * B];        // residual^T [c][b]
__device__ __align__(16) float  g_sim[B * POOL];          // sim [b][p]
__device__ __align__(16) float  g_rsim[B * POOL];         // res-sim [b][p]
__device__ int    g_idx1[B];
__device__ int    g_idx2[B];
__device__ float  g_best1[B];
__device__ float  g_best2[B];

// ---------------------------------------------------------------------------
// 1) Fused: copy x_embed -> out rows [32,2080) AND per-(b,chunk,c) sums.
//    grid = B*32 = 2048, block = 192. Deterministic (no atomics).
// ---------------------------------------------------------------------------
__global__ __launch_bounds__(C4) void copy_mean_kernel(
    const float4* __restrict__ x, float4* __restrict__ out4)
{
    int b     = blockIdx.x >> 5;
    int chunk = blockIdx.x & 31;
    int c4    = threadIdx.x;                         // 0..191

    size_t xbase = ((size_t)b * N + (size_t)chunk * TOKPC) * C4 + c4;
    size_t obase = ((size_t)b * NOUT + 2 * LEN + (size_t)chunk * TOKPC) * C4 + c4;

    float ax = 0.f, ay = 0.f, az = 0.f, aw = 0.f;
#pragma unroll 8
    for (int t = 0; t < TOKPC; ++t) {
        float4 v = x[xbase + (size_t)t * C4];
        out4[obase + (size_t)t * C4] = v;
        ax += v.x; ay += v.y; az += v.z; aw += v.w;
    }
    g_part[(b * NCHUNK + chunk) * C4 + c4] = make_float4(ax, ay, az, aw);
}

// ---------------------------------------------------------------------------
// 2) x_norm = l2norm(mean) -> g_xnormT (transposed).  grid=B, block=256.
// ---------------------------------------------------------------------------
__global__ __launch_bounds__(256) void xnorm_kernel()
{
    __shared__ float sh[8];
    int tid = threadIdx.x;
    int warp = tid >> 5, lane = tid & 31;
    int b = blockIdx.x;
    int c4 = tid;
    float sx = 0.f, sy = 0.f, sz = 0.f, sw = 0.f;
    if (c4 < C4) {
#pragma unroll
        for (int k = 0; k < NCHUNK; ++k) {
            float4 p = g_part[(b * NCHUNK + k) * C4 + c4];
            sx += p.x; sy += p.y; sz += p.z; sw += p.w;
        }
        const float invN = 1.0f / (float)N;
        sx *= invN; sy *= invN; sz *= invN; sw *= invN;
    }
    float ss = sx * sx + sy * sy + sz * sz + sw * sw;
#pragma unroll
    for (int o = 16; o > 0; o >>= 1) ss += __shfl_down_sync(0xffffffffu, ss, o);
    if (lane == 0) sh[warp] = ss;
    __syncthreads();
    if (tid == 0) {
        float tot = 0.f;
#pragma unroll
        for (int w = 0; w < 8; ++w) tot += sh[w];
        sh[0] = rsqrtf(fmaxf(tot, 1e-12f));
    }
    __syncthreads();
    if (c4 < C4) {
        float inv = sh[0];
        int c = c4 * 4;
        g_xnormT[(c + 0) * B + b] = sx * inv;
        g_xnormT[(c + 1) * B + b] = sy * inv;
        g_xnormT[(c + 2) * B + b] = sz * inv;
        g_xnormT[(c + 3) * B + b] = sw * inv;
    }
}

// ---------------------------------------------------------------------------
// 3) sim[b][p] = dot(vec[b], key[p]) * rsqrt(max(||key[p]||^2, eps))
//    Key norms computed INLINE (key rows are streamed anyway).
//    Block handles 2 pool rows; 8 warps split k; lane owns a batch pair.
//    grid = POOL/2 = 512, block = 256.
// ---------------------------------------------------------------------------
template <int STAGE>
__global__ __launch_bounds__(256) void sim_kernel(const float* __restrict__ keys)
{
    const float* vecT = STAGE ? g_residT : g_xnormT;   // [DIM][B]
    float*       simB = STAGE ? g_rsim   : g_sim;      // [B][POOL]

    int p0   = blockIdx.x * 2;
    int warp = threadIdx.x >> 5, lane = threadIdx.x & 31;

    const float*  k0p = keys + (size_t)p0 * DIM;
    const float*  k1p = k0p + DIM;
    const float2* xv  = (const float2*)vecT + lane;    // +k*(B/2)

    float a0x = 0.f, a0y = 0.f, a1x = 0.f, a1y = 0.f;
    float ss0 = 0.f, ss1 = 0.f;                        // identical across lanes
    int kb = warp * KSTRIPE;
#pragma unroll 8
    for (int i = 0; i < KSTRIPE; ++i) {
        int k = kb + i;
        float  kv0 = __ldg(k0p + k);
        float  kv1 = __ldg(k1p + k);
        ss0 += kv0 * kv0;
        ss1 += kv1 * kv1;
        float2 x = xv[(size_t)k * (B / 2)];
        a0x += kv0 * x.x; a0y += kv0 * x.y;
        a1x += kv1 * x.x; a1y += kv1 * x.y;
    }
    __shared__ float4 spart[8][32];
    __shared__ float2 snorm[8];
    spart[warp][lane] = make_float4(a0x, a0y, a1x, a1y);
    if (lane == 0) snorm[warp] = make_float2(ss0, ss1);
    __syncthreads();
    if (warp == 0) {
        float sx = 0.f, sy = 0.f, tx = 0.f, ty = 0.f;
        float n0 = 0.f, n1 = 0.f;
#pragma unroll
        for (int w = 0; w < 8; ++w) {
            float4 v = spart[w][lane];
            sx += v.x; sy += v.y; tx += v.z; ty += v.w;
            n0 += snorm[w].x; n1 += snorm[w].y;
        }
        float i0 = rsqrtf(fmaxf(n0, 1e-12f));
        float i1 = rsqrtf(fmaxf(n1, 1e-12f));
        int b0 = lane * 2;
        simB[(size_t)b0 * POOL + p0]           = sx * i0;
        simB[(size_t)(b0 + 1) * POOL + p0]     = sy * i0;
        simB[(size_t)b0 * POOL + p0 + 1]       = tx * i1;
        simB[(size_t)(b0 + 1) * POOL + p0 + 1] = ty * i1;
    }
}

// ---------------------------------------------------------------------------
// 4) argmax over p (lowest index wins ties). One block per batch; one float4
//    of the sim row per thread (coalesced 4KB). STAGE 0 also builds residT.
//    grid = B, block = 256. NO gather here (moved to finish_kernel).
// ---------------------------------------------------------------------------
template <int STAGE>
__global__ __launch_bounds__(256) void argmax_kernel(const float* __restrict__ pk)
{
    __shared__ float swv[8];
    __shared__ int   swi[8];
    __shared__ int   s_idx;
    int b = blockIdx.x, tid = threadIdx.x;
    int warp = tid >> 5, lane = tid & 31;

    const float* simRow = (STAGE ? g_rsim : g_sim) + (size_t)b * POOL;
    float4 v4 = ((const float4*)simRow)[tid];

    // ascending p with strict > keeps lowest index on ties
    float best = v4.x; int bi = tid * 4;
    if (v4.y > best) { best = v4.y; bi = tid * 4 + 1; }
    if (v4.z > best) { best = v4.z; bi = tid * 4 + 2; }
    if (v4.w > best) { best = v4.w; bi = tid * 4 + 3; }

#pragma unroll
    for (int o = 16; o > 0; o >>= 1) {
        float vo = __shfl_down_sync(0xffffffffu, best, o);
        int   io = __shfl_down_sync(0xffffffffu, bi, o);
        if (vo > best || (vo == best && io < bi)) { best = vo; bi = io; }
    }
    if (lane == 0) { swv[warp] = best; swi[warp] = bi; }
    __syncthreads();
    if (tid == 0) {
        float v = swv[0]; int id = swi[0];
#pragma unroll
        for (int w = 1; w < 8; ++w) {
            if (swv[w] > v || (swv[w] == v && swi[w] < id)) {
                v = swv[w]; id = swi[w];
            }
        }
        s_idx = id;
        if (STAGE) { g_idx2[b] = id; g_best2[b] = v; }
        else       { g_idx1[b] = id; g_best1[b] = v; }
    }
    if (!STAGE) {
        __syncthreads();
        int idx = s_idx;
        // residT[c][b] = pk[idx][c] - xnormT[c][b]
#pragma unroll
        for (int i = 0; i < 3; ++i) {
            int c = tid + i * 256;
            g_residT[c * B + b] = pk[(size_t)idx * DIM + c] - g_xnormT[c * B + b];
        }
    }
}

// ---------------------------------------------------------------------------
// 5) finish: both gathers spread over 256 blocks + scalar in block 256.
//    block (b, which, half): copies 8 prompt rows (1536 float4).
//    which=0 -> residual_prompt[g_idx2] @ out rows [0,16)
//    which=1 -> prompt[g_idx1]          @ out rows [16,32)
// ---------------------------------------------------------------------------
__global__ __launch_bounds__(256) void finish_kernel(
    const float4* __restrict__ prompt4,
    const float4* __restrict__ rprompt4,
    float4* __restrict__ out4,
    float* __restrict__ out_scalar,
    int write_scalar)
{
    if (blockIdx.x == 4 * B) {
        __shared__ float sh[2];
        if (write_scalar && threadIdx.x < 64) {
            float v = g_best1[threadIdx.x] + g_best2[threadIdx.x];
#pragma unroll
            for (int o = 16; o > 0; o >>= 1)
                v += __shfl_down_sync(0xffffffffu, v, o);
            if ((threadIdx.x & 31) == 0) sh[threadIdx.x >> 5] = v;
        }
        __syncthreads();
        if (write_scalar && threadIdx.x == 0)
            out_scalar[SCALAR_OFF] = (sh[0] + sh[1]) * (1.0f / (float)B);
        return;
    }
    int b     = blockIdx.x >> 2;
    int which = (blockIdx.x >> 1) & 1;
    int half  = blockIdx.x & 1;
    int idx = which ? g_idx1[b] : g_idx2[b];
    const int HQ = (LEN / 2) * C4;                   // 1536 float4 per half
    const float4* src = (which ? prompt4 : rprompt4)
                        + (size_t)idx * LEN * C4 + (size_t)half * HQ;
    float4* dst = out4 + ((size_t)b * NOUT + (which ? LEN : 0)
                          + (size_t)half * (LEN / 2)) * C4;
#pragma unroll
    for (int i = 0; i < HQ / 256; ++i)
        dst[threadIdx.x + i * 256] = src[threadIdx.x + i * 256];
}

// ---------------------------------------------------------------------------
// launch
// ---------------------------------------------------------------------------
extern "C" void kernel_launch(void* const* d_in, const int* in_sizes, int n_in,
                              void* d_out, int out_size)
{
    // Map inputs by element count (order-robust).
    const float* x_embed = nullptr;
    const float* prompt = nullptr, * rprompt = nullptr;
    const float* pkey = nullptr, * rpkey = nullptr;
    for (int i = 0; i < n_in; ++i) {
        int sz = in_sizes[i];
        if (sz == B * N * DIM) x_embed = (const float*)d_in[i];
        else if (sz == POOL * LEN * DIM) {
            if (!prompt) prompt = (const float*)d_in[i];
            else if (!rprompt) rprompt = (const float*)d_in[i];
        } else if (sz == POOL * DIM) {
            if (!pkey) pkey = (const float*)d_in[i];
            else if (!rpkey) rpkey = (const float*)d_in[i];
        }
    }
    float* out = (float*)d_out;

    copy_mean_kernel<<<B * NCHUNK, C4>>>((const float4*)x_embed, (float4*)out);
    xnorm_kernel<<<B, 256>>>();
    sim_kernel<0><<<POOL / 2, 256>>>(pkey);
    argmax_kernel<0><<<B, 256>>>(pkey);
    sim_kernel<1><<<POOL / 2, 256>>>(rpkey);
    argmax_kernel<1><<<B, 256>>>(nullptr);
    int write_scalar = ((size_t)out_size > SCALAR_OFF) ? 1 : 0;
    finish_kernel<<<4 * B + 1, 256>>>(
        (const float4*)prompt, (const float4*)rprompt, (float4*)out,
        out, write_scalar);
}